// round 17
// baseline (speedup 1.0000x reference)
#include <cuda_runtime.h>
#include <cuda_fp16.h>

#define NN   50000
#define NNP  50048
#define NE   400000
#define INF  50
#define HID  512
#define OUTF 121
#define EPSF 1e-5f
#define NSB  49

// ---------------- device scratch ----------------
__device__ float g_invdeg[NN];
__device__ __half g_hh[(size_t)NNP * HID];    // inter-layer h (fp16)
__device__ __half g_aggh[(size_t)NNP * HID];  // aggregated neighbors (fp16)
__device__ __half g_xh[(size_t)NNP * 64];
__device__ __half g_a1h[(size_t)NNP * 64];

#define OFF_WL1 0
#define OFF_WR1 32768
#define OFF_WL2 65536
#define OFF_WR2 327680
#define OFF_WL3 589824
#define OFF_WR3 851968
#define OFF_WL4 1114112
#define OFF_WR4 1179648
#define WTOT    1245184
__device__ __half g_wh[WTOT];   // weights: exact hi+lo split
__device__ __half g_wl[WTOT];

__device__ float g_colsum[3 * HID], g_colsq[3 * HID];
__device__ int g_src[NE], g_dst[NE], g_csrc[NE];
__device__ int g_rowptr[NN + 1], g_cnt[NN], g_cursor[NN], g_is64;
__device__ int g_blksum[64], g_blkoff[64];

// ---------------- helpers ----------------
__device__ __forceinline__ unsigned s2u(const void* p) {
    unsigned a;
    asm("{ .reg .u64 t; cvta.to.shared.u64 t, %1; cvt.u32.u64 %0, t; }" : "=r"(a) : "l"(p));
    return a;
}
__device__ __forceinline__ void cp16(unsigned dst, const void* src) {
    asm volatile("cp.async.cg.shared.global [%0], [%1], 16;" :: "r"(dst), "l"(src));
}
__device__ __forceinline__ void split1(float v, __half& hi, __half& lo) {
    hi = __float2half_rn(v);
    lo = __float2half_rn(v - __half2float(hi));
}
__device__ __forceinline__ float4 ldh4cg(const __half* p) {
    uint2 u = __ldcg((const uint2*)p);
    __half2 a = *(__half2*)&u.x;
    __half2 b = *(__half2*)&u.y;
    float2 fa = __half22float2(a);
    float2 fb = __half22float2(b);
    return make_float4(fa.x, fa.y, fb.x, fb.y);
}
__device__ __forceinline__ void mma_f16(float* c,
                                        unsigned a0, unsigned a1, unsigned a2, unsigned a3,
                                        unsigned b0, unsigned b1) {
    asm volatile(
        "mma.sync.aligned.m16n8k16.row.col.f32.f16.f16.f32 "
        "{%0,%1,%2,%3},{%4,%5,%6,%7},{%8,%9},{%0,%1,%2,%3};"
        : "+f"(c[0]), "+f"(c[1]), "+f"(c[2]), "+f"(c[3])
        : "r"(a0), "r"(a1), "r"(a2), "r"(a3), "r"(b0), "r"(b1));
}

// ---------------- prep ----------------
__global__ void prep0_k() {
    int i = blockIdx.x * blockDim.x + threadIdx.x;
    if (i == 0) g_is64 = 1;
    if (i < NN) g_cnt[i] = 0;
    if (i < 3 * HID) { g_colsum[i] = 0.f; g_colsq[i] = 0.f; }
}
__global__ void detect_idx_k(const long long* __restrict__ ei) {
    int stride = gridDim.x * blockDim.x;
    int bad = 0;
    for (int i = blockIdx.x * blockDim.x + threadIdx.x; i < NE; i += stride) {
        long long v = ei[i];
        if (v < 0 || v >= NN) { bad = 1; break; }
    }
    if (__syncthreads_or(bad)) {
        if (threadIdx.x == 0) atomicExch(&g_is64, 0);
    }
}
__global__ void convert_count_k(const void* __restrict__ ei) {
    int e = blockIdx.x * blockDim.x + threadIdx.x;
    if (e >= NE) return;
    int s, d;
    if (g_is64) {
        const long long* p = (const long long*)ei;
        s = (int)p[e]; d = (int)p[e + NE];
    } else {
        const int* p = (const int*)ei;
        s = p[e]; d = p[e + NE];
    }
    s = min(max(s, 0), NN - 1);
    d = min(max(d, 0), NN - 1);
    g_src[e] = s;
    g_dst[e] = d;
    atomicAdd(&g_cnt[d], 1);
}
__global__ void scan1_k() {
    __shared__ int sh[1024];
    int tid = threadIdx.x;
    int i = blockIdx.x * 1024 + tid;
    int v = (i < NN) ? g_cnt[i] : 0;
    sh[tid] = v;
    __syncthreads();
#pragma unroll
    for (int off = 1; off < 1024; off <<= 1) {
        int x = (tid >= off) ? sh[tid - off] : 0;
        __syncthreads();
        sh[tid] += x;
        __syncthreads();
    }
    if (i < NN) g_rowptr[i] = sh[tid] - v;
    if (tid == 1023) g_blksum[blockIdx.x] = sh[1023];
}
__global__ void scan2_k() {
    __shared__ int sh[64];
    int t = threadIdx.x;
    int v = (t < NSB) ? g_blksum[t] : 0;
    sh[t] = v;
    __syncthreads();
#pragma unroll
    for (int off = 1; off < 64; off <<= 1) {
        int x = (t >= off) ? sh[t - off] : 0;
        __syncthreads();
        sh[t] += x;
        __syncthreads();
    }
    if (t < 64) g_blkoff[t] = sh[t] - v;
}
__global__ void scan3_k() {
    int i = blockIdx.x * blockDim.x + threadIdx.x;
    if (i >= NN) return;
    g_rowptr[i] += g_blkoff[i >> 10];
    g_cursor[i] = 0;
    g_invdeg[i] = 1.0f / (float)max(g_cnt[i], 1);
    if (i == 0) g_rowptr[NN] = g_blkoff[NSB - 1] + g_blksum[NSB - 1];
}
__global__ void fill_k() {
    int e = blockIdx.x * blockDim.x + threadIdx.x;
    if (e >= NE) return;
    int d = g_dst[e];
    int slot = g_rowptr[d] + atomicAdd(&g_cursor[d], 1);
    g_csrc[slot] = g_src[e];
}

// ---------------- unified plane split (weights hi+lo; x hi only) ----------------
#define XTOT (NN * 64)
__global__ void split_all_k(const float* __restrict__ Wl1, const float* __restrict__ Wr1,
                            const float* __restrict__ Wl2, const float* __restrict__ Wr2,
                            const float* __restrict__ Wl3, const float* __restrict__ Wr3,
                            const float* __restrict__ Wl4, const float* __restrict__ Wr4,
                            const float* __restrict__ x) {
    int idx = blockIdx.x * blockDim.x + threadIdx.x;
    if (idx >= WTOT + XTOT) return;
    if (idx >= WTOT) {
        int i = idx - WTOT;
        int n = i >> 6, c = i & 63;
        float v = (c < INF) ? x[(size_t)n * INF + c] : 0.f;
        g_xh[i] = __float2half_rn(v);
        return;
    }
    const float* W;
    int off, Kpad, K, N;
    if (idx < OFF_WL2) {
        Kpad = 64; K = INF; N = HID;
        if (idx < OFF_WR1) { W = Wl1; off = OFF_WL1; }
        else               { W = Wr1; off = OFF_WR1; }
    } else if (idx < OFF_WL4) {
        Kpad = 512; K = HID; N = HID;
        if (idx < OFF_WR2)      { W = Wl2; off = OFF_WL2; }
        else if (idx < OFF_WL3) { W = Wr2; off = OFF_WR2; }
        else if (idx < OFF_WR3) { W = Wl3; off = OFF_WL3; }
        else                    { W = Wr3; off = OFF_WR3; }
    } else {
        Kpad = 512; K = HID; N = OUTF;
        if (idx < OFF_WR4) { W = Wl4; off = OFF_WL4; }
        else               { W = Wr4; off = OFF_WR4; }
    }
    int local = idx - off;
    int n = local / Kpad, k = local - n * Kpad;
    float v = (n < N && k < K) ? W[(size_t)k * N + n] : 0.f;
    __half hi, lo;
    split1(v, hi, lo);
    g_wh[idx] = hi;
    g_wl[idx] = lo;
}

// ---------------- layer-1 gather (4 nodes / 256-thread block) ----------------
__global__ void gather50_k(const float* __restrict__ x) {
    int node = blockIdx.x * 4 + (threadIdx.x >> 6);
    int t = threadIdx.x & 63;
    if (node >= NN) return;
    float acc = 0.f;
    if (t < INF) {
        int beg = g_rowptr[node], end = g_rowptr[node + 1];
        for (int e = beg; e < end; ++e) acc += x[(size_t)g_csrc[e] * INF + t];
        acc *= g_invdeg[node];
    }
    g_a1h[(size_t)node * 64 + t] = __float2half_rn(acc);
}

// ---------------- fused gather + inline-BN (agg only; hb eliminated) ----------------
__global__ void __launch_bounds__(256, 8)
gather_bn_k(const float* __restrict__ gamma, const float* __restrict__ beta, int si) {
    int half_ = threadIdx.x >> 7;
    int tid = threadIdx.x & 127;
    int node = blockIdx.x * 2 + half_;
    if (node >= NN) return;
    size_t coff = (size_t)tid * 4;

    float4 cs = *(const float4*)(g_colsum + si * HID + coff);
    float4 cq = *(const float4*)(g_colsq + si * HID + coff);
    float4 ga = *(const float4*)(gamma + coff);
    float4 be = *(const float4*)(beta + coff);
    const float invn = 1.0f / NN;
    float4 sc, sh;
    {
        float m, r;
        m = cs.x * invn; r = rsqrtf(cq.x * invn - m * m + EPSF); sc.x = r * ga.x; sh.x = be.x - m * sc.x;
        m = cs.y * invn; r = rsqrtf(cq.y * invn - m * m + EPSF); sc.y = r * ga.y; sh.y = be.y - m * sc.y;
        m = cs.z * invn; r = rsqrtf(cq.z * invn - m * m + EPSF); sc.z = r * ga.z; sh.z = be.z - m * sc.z;
        m = cs.w * invn; r = rsqrtf(cq.w * invn - m * m + EPSF); sc.w = r * ga.w; sh.w = be.w - m * sc.w;
    }

    int beg = g_rowptr[node], end = g_rowptr[node + 1];
    float a0 = 0.f, a1 = 0.f, a2 = 0.f, a3 = 0.f;
    int e = beg;
#define GB_ACC(v) \
    a0 += fmaxf(fmaf((v).x, sc.x, sh.x), 0.f); \
    a1 += fmaxf(fmaf((v).y, sc.y, sh.y), 0.f); \
    a2 += fmaxf(fmaf((v).z, sc.z, sh.z), 0.f); \
    a3 += fmaxf(fmaf((v).w, sc.w, sh.w), 0.f)
    for (; e + 7 < end; e += 8) {
        float4 v0 = ldh4cg(g_hh + (size_t)g_csrc[e]     * HID + coff);
        float4 v1 = ldh4cg(g_hh + (size_t)g_csrc[e + 1] * HID + coff);
        float4 v2 = ldh4cg(g_hh + (size_t)g_csrc[e + 2] * HID + coff);
        float4 v3 = ldh4cg(g_hh + (size_t)g_csrc[e + 3] * HID + coff);
        float4 v4 = ldh4cg(g_hh + (size_t)g_csrc[e + 4] * HID + coff);
        float4 v5 = ldh4cg(g_hh + (size_t)g_csrc[e + 5] * HID + coff);
        float4 v6 = ldh4cg(g_hh + (size_t)g_csrc[e + 6] * HID + coff);
        float4 v7 = ldh4cg(g_hh + (size_t)g_csrc[e + 7] * HID + coff);
        GB_ACC(v0); GB_ACC(v1); GB_ACC(v2); GB_ACC(v3);
        GB_ACC(v4); GB_ACC(v5); GB_ACC(v6); GB_ACC(v7);
    }
    for (; e + 3 < end; e += 4) {
        float4 v0 = ldh4cg(g_hh + (size_t)g_csrc[e]     * HID + coff);
        float4 v1 = ldh4cg(g_hh + (size_t)g_csrc[e + 1] * HID + coff);
        float4 v2 = ldh4cg(g_hh + (size_t)g_csrc[e + 2] * HID + coff);
        float4 v3 = ldh4cg(g_hh + (size_t)g_csrc[e + 3] * HID + coff);
        GB_ACC(v0); GB_ACC(v1); GB_ACC(v2); GB_ACC(v3);
    }
    for (; e < end; ++e) {
        float4 v0 = ldh4cg(g_hh + (size_t)g_csrc[e] * HID + coff);
        GB_ACC(v0);
    }
#undef GB_ACC
    float inv = g_invdeg[node];
    __half2 p0 = __floats2half2_rn(a0 * inv, a1 * inv);
    __half2 p1 = __floats2half2_rn(a2 * inv, a3 * inv);
    size_t o = (size_t)node * HID + coff;
    *(uint2*)(g_aggh + o) = make_uint2(*(unsigned*)&p0, *(unsigned*)&p1);
}

// ---------------- dual GEMM: A via LDG(+BN transform)->STS, B hi+lo via cp.async ----------------
#define AW2 36
#define ASZ2 (128 * AW2)

template <int NI>
__global__ void __launch_bounds__(512, 1)
gemm_k(int aSel, int K1, int K2, int woff1, int woff2,
       const float* __restrict__ bias, int N, int cSel, float* __restrict__ cExt,
       int si, const float* __restrict__ gammaA, const float* __restrict__ betaA, int siA) {
    constexpr int BN = NI * 32;
    constexpr int BSZ = BN * AW2;
    constexpr int STGU = ASZ2 + 2 * BSZ;

    extern __shared__ unsigned sm[];
    unsigned sbase = s2u(sm);
    __shared__ float s_sum[BN], s_sq[BN];
    __shared__ float s_bnc[HID], s_bns[HID];   // BN coefficients for A2 transform

    const __half *A1, *A2;
    if (aSel == 0) { A1 = g_a1h; A2 = g_xh; }
    else           { A1 = g_aggh; A2 = g_hh; }
    const __half* B1h = g_wh + woff1;
    const __half* B1l = g_wl + woff1;
    const __half* B2h = g_wh + woff2;
    const __half* B2l = g_wl + woff2;
    bool doStat = (si >= 0);
    bool doBN = (aSel == 1);

    int tid = threadIdx.x;
    int warp = tid >> 5, lane = tid & 31;
    int wm = warp & 3, wn = warp >> 2;
    int g = lane >> 2, t = lane & 3;
    int row0 = blockIdx.y * 128;
    int col0 = blockIdx.x * BN;

    int S1 = K1 >> 6, S2 = K2 >> 6, S = S1 + S2;

    // BN coefficients for the A2 transform (features of g_hh)
    if (doBN && tid < HID) {
        float m = g_colsum[siA * HID + tid] * (1.0f / NN);
        float var = g_colsq[siA * HID + tid] * (1.0f / NN) - m * m;
        float r = rsqrtf(var + EPSF);
        float scv = r * gammaA[tid];
        s_bnc[tid] = scv;
        s_bns[tid] = betaA[tid] - m * scv;
    }
    if (doStat && tid < BN) { s_sum[tid] = 0.f; s_sq[tid] = 0.f; }
    if (doBN) __syncthreads();   // s_bnc/s_bns ready before first stsA

    float acc[2][NI][4];
#pragma unroll
    for (int mi = 0; mi < 2; mi++)
#pragma unroll
        for (int ni = 0; ni < NI; ni++)
#pragma unroll
            for (int r = 0; r < 4; r++) acc[mi][ni][r] = 0.f;

    int arow = tid >> 3, ach = tid & 7;   // A: each thread does rows arow, arow+64

    uint2 aR[2][2];

    auto prefetchB = [&](int s, int buf) {
        const __half *Bh, *Bl;
        int ka, k0;
        if (s < S1) { Bh = B1h; Bl = B1l; ka = K1; k0 = s * 64; }
        else        { Bh = B2h; Bl = B2l; ka = K2; k0 = (s - S1) * 64; }
        unsigned base = sbase + buf * (STGU * 4);
#pragma unroll
        for (int l = 0; l < BN / 64; l++) {
            int idx = tid + l * 512;
            int row = idx >> 3, ch = idx & 7;
            unsigned d = base + ASZ2 * 4 + row * (AW2 * 4) + ch * 16;
            size_t boff = (size_t)(col0 + row) * ka + k0 + ch * 8;
            cp16(d, Bh + boff);
            cp16(d + BSZ * 4, Bl + boff);
        }
        asm volatile("cp.async.commit_group;" ::: "memory");
    };

    auto ldgA = [&](int s) {
        const __half* Aa = (s < S1) ? A1 : A2;
        int ka = (s < S1) ? K1 : K2;
        int k0 = (s < S1) ? s * 64 : (s - S1) * 64;
#pragma unroll
        for (int l = 0; l < 2; l++) {
            const __half* src = Aa + (size_t)(row0 + arow + l * 64) * ka + k0 + ach * 8;
            aR[l][0] = __ldg((const uint2*)src);
            aR[l][1] = __ldg((const uint2*)src + 1);
        }
    };

    auto stsA = [&](int s, int buf) {
        bool xform = doBN && (s >= S1);
        int k0 = (s < S1) ? s * 64 : (s - S1) * 64;
#pragma unroll
        for (int l = 0; l < 2; l++) {
            unsigned w0 = aR[l][0].x, w1 = aR[l][0].y, w2 = aR[l][1].x, w3 = aR[l][1].y;
            if (xform) {
                int kb = k0 + ach * 8;
#pragma unroll
                for (int j = 0; j < 4; j++) {
                    unsigned* wp = (j == 0) ? &w0 : (j == 1) ? &w1 : (j == 2) ? &w2 : &w3;
                    __half2 hv = *(__half2*)wp;
                    float2 f = __half22float2(hv);
                    float r0 = fmaxf(fmaf(f.x, s_bnc[kb + 2 * j], s_bns[kb + 2 * j]), 0.f);
                    float r1 = fmaxf(fmaf(f.y, s_bnc[kb + 2 * j + 1], s_bns[kb + 2 * j + 1]), 0.f);
                    __half2 o = __floats2half2_rn(r0, r1);
                    *wp = *(unsigned*)&o;
                }
            }
            int di = buf * STGU + (arow + l * 64) * AW2 + ach * 4;
            *(uint4*)&sm[di] = make_uint4(w0, w1, w2, w3);
        }
    };

    auto compute = [&](int buf) {
        const unsigned* Ah = sm + buf * STGU;
        const unsigned* Bh = Ah + ASZ2;
        const unsigned* Bl = Bh + BSZ;
#pragma unroll
        for (int ks = 0; ks < 4; ks++) {
            int kb = ks * 8;
            unsigned ah[2][4];
#pragma unroll
            for (int mi = 0; mi < 2; mi++) {
                int rb = wm * 32 + mi * 16;
                int i0 = (rb + g) * AW2 + kb + t;
                int i1 = (rb + g + 8) * AW2 + kb + t;
                ah[mi][0] = Ah[i0];
                ah[mi][1] = Ah[i1];
                ah[mi][2] = Ah[i0 + 4];
                ah[mi][3] = Ah[i1 + 4];
            }
#pragma unroll
            for (int ni = 0; ni < NI; ni++) {
                int cb = (wn * (NI * 8) + ni * 8 + g) * AW2 + kb + t;
                unsigned b0 = Bh[cb], b1 = Bh[cb + 4];
                unsigned c0 = Bl[cb], c1 = Bl[cb + 4];
#pragma unroll
                for (int mi = 0; mi < 2; mi++) {
                    float* c = acc[mi][ni];
                    mma_f16(c, ah[mi][0], ah[mi][1], ah[mi][2], ah[mi][3], b0, b1);
                    mma_f16(c, ah[mi][0], ah[mi][1], ah[mi][2], ah[mi][3], c0, c1);
                }
            }
        }
    };

    // pipeline: B cp.async + A register-staged LDG->STS
    prefetchB(0, 0);
    ldgA(0);
    stsA(0, 0);
#pragma unroll 1
    for (int s = 0; s < S; s++) {
        asm volatile("cp.async.wait_group 0;" ::: "memory");
        __syncthreads();                       // B(s) + A(s) STS visible
        if (s + 1 < S) { prefetchB(s + 1, (s + 1) & 1); ldgA(s + 1); }
        compute(s & 1);
        if (s + 1 < S) stsA(s + 1, (s + 1) & 1);
    }

    if (doStat) __syncthreads();

    float colS[NI][2], colQ[NI][2];
#pragma unroll
    for (int ni = 0; ni < NI; ni++) {
        colS[ni][0] = colS[ni][1] = 0.f;
        colQ[ni][0] = colQ[ni][1] = 0.f;
    }
#pragma unroll
    for (int mi = 0; mi < 2; mi++) {
        int ra = row0 + wm * 32 + mi * 16 + g;
        int rb = ra + 8;
        bool va = ra < NN, vb = rb < NN;
#pragma unroll
        for (int ni = 0; ni < NI; ni++) {
            int col = col0 + wn * (NI * 8) + ni * 8 + t * 2;
            float* c = acc[mi][ni];
            if (col + 1 < N) {
                float b0 = __ldg(&bias[col]);
                float b1 = __ldg(&bias[col + 1]);
                float v0 = c[0] + b0, v1 = c[1] + b1;
                float v2 = c[2] + b0, v3 = c[3] + b1;
                if (cSel == 1) {
                    if (va) *(__half2*)(g_hh + (size_t)ra * N + col) = __floats2half2_rn(v0, v1);
                    if (vb) *(__half2*)(g_hh + (size_t)rb * N + col) = __floats2half2_rn(v2, v3);
                } else {
                    if (va) { cExt[(size_t)ra * N + col] = v0; cExt[(size_t)ra * N + col + 1] = v1; }
                    if (vb) { cExt[(size_t)rb * N + col] = v2; cExt[(size_t)rb * N + col + 1] = v3; }
                }
                if (va) { colS[ni][0] += v0; colQ[ni][0] += v0 * v0;
                          colS[ni][1] += v1; colQ[ni][1] += v1 * v1; }
                if (vb) { colS[ni][0] += v2; colQ[ni][0] += v2 * v2;
                          colS[ni][1] += v3; colQ[ni][1] += v3 * v3; }
            } else if (col < N) {
                float b0 = __ldg(&bias[col]);
                float v0 = c[0] + b0, v2 = c[2] + b0;
                if (cSel == 1) {
                    if (va) g_hh[(size_t)ra * N + col] = __float2half_rn(v0);
                    if (vb) g_hh[(size_t)rb * N + col] = __float2half_rn(v2);
                } else {
                    if (va) cExt[(size_t)ra * N + col] = v0;
                    if (vb) cExt[(size_t)rb * N + col] = v2;
                }
                if (va) { colS[ni][0] += v0; colQ[ni][0] += v0 * v0; }
                if (vb) { colS[ni][0] += v2; colQ[ni][0] += v2 * v2; }
            }
        }
    }

    if (doStat) {
#pragma unroll
        for (int ni = 0; ni < NI; ni++)
#pragma unroll
            for (int p = 0; p < 2; p++) {
#pragma unroll
                for (int off = 4; off < 32; off <<= 1) {
                    colS[ni][p] += __shfl_xor_sync(0xFFFFFFFF, colS[ni][p], off);
                    colQ[ni][p] += __shfl_xor_sync(0xFFFFFFFF, colQ[ni][p], off);
                }
            }
        if (g == 0) {
#pragma unroll
            for (int ni = 0; ni < NI; ni++) {
                int ci = wn * (NI * 8) + ni * 8 + t * 2;
                atomicAdd(&s_sum[ci], colS[ni][0]);
                atomicAdd(&s_sq[ci], colQ[ni][0]);
                atomicAdd(&s_sum[ci + 1], colS[ni][1]);
                atomicAdd(&s_sq[ci + 1], colQ[ni][1]);
            }
        }
        __syncthreads();
        if (tid < BN) {
            atomicAdd(&g_colsum[si * HID + col0 + tid], s_sum[tid]);
            atomicAdd(&g_colsq[si * HID + col0 + tid], s_sq[tid]);
        }
    }
}

#define GEMM_SMEM8 ((ASZ2 + 2 * 256 * AW2) * 4 * 2)   // 184320 B
#define GEMM_SMEM4 ((ASZ2 + 2 * 128 * AW2) * 4 * 2)   // 110592 B

// ---------------- host ----------------
static inline int cdiv(long long a, int b) { return (int)((a + b - 1) / b); }

extern "C" void kernel_launch(void* const* d_in, const int* in_sizes, int n_in,
                              void* d_out, int out_size) {
    const float* x = (const float*)d_in[0];
    const void* ei = d_in[1];

    const float* Wl[4] = {(const float*)d_in[2], (const float*)d_in[5],
                          (const float*)d_in[8], (const float*)d_in[11]};
    const float* bl[4] = {(const float*)d_in[3], (const float*)d_in[6],
                          (const float*)d_in[9], (const float*)d_in[12]};
    const float* Wr[4] = {(const float*)d_in[4], (const float*)d_in[7],
                          (const float*)d_in[10], (const float*)d_in[13]};
    const float* gam[3] = {(const float*)d_in[14], (const float*)d_in[16], (const float*)d_in[18]};
    const float* bet[3] = {(const float*)d_in[15], (const float*)d_in[17], (const float*)d_in[19]};
    float* out = (float*)d_out;

    cudaFuncSetAttribute(gemm_k<8>, cudaFuncAttributeMaxDynamicSharedMemorySize, GEMM_SMEM8);
    cudaFuncSetAttribute(gemm_k<4>, cudaFuncAttributeMaxDynamicSharedMemorySize, GEMM_SMEM4);

    // edge indices + CSR
    prep0_k<<<cdiv(NN, 256), 256>>>();
    detect_idx_k<<<128, 1024>>>((const long long*)ei);
    convert_count_k<<<cdiv(NE, 256), 256>>>(ei);
    scan1_k<<<NSB, 1024>>>();
    scan2_k<<<1, 64>>>();
    scan3_k<<<cdiv(NN, 256), 256>>>();
    fill_k<<<cdiv(NE, 256), 256>>>();
    split_all_k<<<cdiv(WTOT + XTOT, 256), 256>>>(Wl[0], Wr[0], Wl[1], Wr[1],
                                                 Wl[2], Wr[2], Wl[3], Wr[3], x);

    dim3 gwide(2, cdiv(NNP, 128));

    // ---- layer 1 (no A transform) ----
    gather50_k<<<cdiv(NN, 4), 256>>>(x);
    gemm_k<8><<<gwide, 512, GEMM_SMEM8>>>(0, 64, 64, OFF_WL1, OFF_WR1, bl[0], HID, 1, nullptr,
                                          0, nullptr, nullptr, 0);

    // ---- layers 2 & 3 (A2 = g_hh with BN(L-1) transform) ----
    for (int L = 1; L <= 2; ++L) {
        int wl = (L == 1) ? OFF_WL2 : OFF_WL3;
        int wr = (L == 1) ? OFF_WR2 : OFF_WR3;
        gather_bn_k<<<NN / 2, 256>>>(gam[L - 1], bet[L - 1], L - 1);
        gemm_k<8><<<gwide, 512, GEMM_SMEM8>>>(1, 512, 512, wl, wr, bl[L], HID, 1, nullptr,
                                              L, gam[L - 1], bet[L - 1], L - 1);
    }

    // ---- layer 4 -> d_out (A2 = g_hh with BN(3) transform) ----
    gather_bn_k<<<NN / 2, 256>>>(gam[2], bet[2], 2);
    gemm_k<4><<<dim3(1, cdiv(NNP, 128)), 512, GEMM_SMEM4>>>(1, 512, 512, OFF_WL4, OFF_WR4,
                                                            bl[3], OUTF, 0, out,
                                                            -1, gam[2], bet[2], 2);
}